// round 11
// baseline (speedup 1.0000x reference)
#include <cuda_runtime.h>
#include <cuda_fp16.h>
#include <cuda_pipeline.h>

// Problem constants
#define CB 4
#define CS 2048
#define CD 1024
#define CH 16
#define CHD 64
#define CBH (CB*CH)

// Scratch (allocation-free)
__device__ __align__(16) __half g_qkv[(size_t)3*CBH*CS*CHD]; // [3][BH][S][HD]
__device__ __align__(16) __half g_y [(size_t)CB*CS*CD];      // [B][S][D]
__device__ __align__(16) __half g_xh[(size_t)CB*CS*CD];
__device__ __align__(16) __half g_wa[(size_t)CD*3*CD];
__device__ __align__(16) __half g_wp[(size_t)CD*CD];

// ---------------------------------------------------------------------------
// One fused fp32 -> fp16 conversion pass over x, Wa, Wp.
// ---------------------------------------------------------------------------
#define N4_X  (CB*CS*CD/4)
#define N4_WA (3*CD*CD/4)
#define N4_WP (CD*CD/4)

__global__ void cvt_all_kernel(const float* __restrict__ x,
                               const float* __restrict__ Wa,
                               const float* __restrict__ Wp,
                               __half* __restrict__ xh,
                               __half* __restrict__ wa,
                               __half* __restrict__ wp)
{
    const int i = blockIdx.x * blockDim.x + threadIdx.x;
    const float4* src;
    __half* dst;
    int j = i;
    if (i < N4_X)                      { src = (const float4*)x;  dst = xh; }
    else if (i < N4_X + N4_WA)         { src = (const float4*)Wa; dst = wa; j = i - N4_X; }
    else if (i < N4_X + N4_WA + N4_WP) { src = (const float4*)Wp; dst = wp; j = i - N4_X - N4_WA; }
    else return;
    float4 v = src[j];
    __half2 lo = __floats2half2_rn(v.x, v.y);
    __half2 hi = __floats2half2_rn(v.z, v.w);
    uint2 u;
    u.x = *(unsigned int*)&lo;
    u.y = *(unsigned int*)&hi;
    ((uint2*)dst)[j] = u;
}

// ---------------------------------------------------------------------------
// Raw-mma helpers
// ---------------------------------------------------------------------------
__device__ __forceinline__ void ldsm4(unsigned* d, unsigned a) {
    asm volatile("ldmatrix.sync.aligned.m8n8.x4.shared.b16 {%0,%1,%2,%3}, [%4];"
        : "=r"(d[0]), "=r"(d[1]), "=r"(d[2]), "=r"(d[3]) : "r"(a));
}
__device__ __forceinline__ void ldsm4t(unsigned* d, unsigned a) {
    asm volatile("ldmatrix.sync.aligned.m8n8.x4.trans.shared.b16 {%0,%1,%2,%3}, [%4];"
        : "=r"(d[0]), "=r"(d[1]), "=r"(d[2]), "=r"(d[3]) : "r"(a));
}
__device__ __forceinline__ void mma16816(float* c, const unsigned* a,
                                         unsigned b0, unsigned b1) {
    asm volatile(
        "mma.sync.aligned.m16n8k16.row.col.f32.f16.f16.f32 "
        "{%0,%1,%2,%3}, {%4,%5,%6,%7}, {%8,%9}, {%0,%1,%2,%3};"
        : "+f"(c[0]), "+f"(c[1]), "+f"(c[2]), "+f"(c[3])
        : "r"(a[0]), "r"(a[1]), "r"(a[2]), "r"(a[3]), "r"(b0), "r"(b1));
}
__device__ __forceinline__ unsigned h2pack(float a, float b) {
    __half2 h = __floats2half2_rn(a, b);
    return *(unsigned*)&h;
}
__device__ __forceinline__ unsigned hex2(unsigned x) {   // 2^x on packed half2
    unsigned d;
    asm("ex2.approx.f16x2 %0, %1;" : "=r"(d) : "r"(x));
    return d;
}

// ---------------------------------------------------------------------------
// Raw-mma FP16 GEMM, cp.async 4-stage, BK=32: C = A[M,K]@B[K,N] + bias.
// CTA 128x128, 8 warps (4m x 2n), warp tile 32x64, direct reg->global epilogue.
// MODE 0: fp32 row-major store. MODE 1: fp16 scatter to [3][BH][S][HD].
// ---------------------------------------------------------------------------
#define BK 32
#define ALD 40
#define BLD 136
#define ST_HALFS (128*ALD + BK*BLD)
#define GEMM_SMEM (4*ST_HALFS*2)

template<int MODE>
__global__ void __launch_bounds__(256, 2) gemm_r(
    const __half* __restrict__ A, const __half* __restrict__ Bm,
    const float* __restrict__ bias, void* __restrict__ Cout,
    int M, int N, int K)
{
    extern __shared__ __half hsm[];
    const int tid = threadIdx.x;
    const int warp = tid >> 5, lane = tid & 31;
    const int wm = warp & 3, wn = warp >> 2;
    const int g = lane >> 2, tg = lane & 3;
    const int m0 = blockIdx.y * 128, n0 = blockIdx.x * 128;

    float acc[2][8][4];
    #pragma unroll
    for (int i = 0; i < 2; i++)
        #pragma unroll
        for (int j = 0; j < 8; j++)
            #pragma unroll
            for (int q = 0; q < 4; q++) acc[i][j][q] = 0.f;

    auto issue = [&](int it) {
        __half* As = hsm + (it & 3) * ST_HALFS;   // [128][ALD]
        __half* Bs = As + 128*ALD;                // [BK][BLD]
        const int k0 = it * BK;
        #pragma unroll
        for (int i = 0; i < 2; i++) {             // A: 512 chunks of 8 halves
            const int c = i * 256 + tid;
            const int row = c >> 2, kc = (c & 3) << 3;
            __pipeline_memcpy_async(&As[row * ALD + kc],
                &A[(size_t)(m0 + row) * K + k0 + kc], 16);
        }
        #pragma unroll
        for (int i = 0; i < 2; i++) {             // B: 512 chunks
            const int c = i * 256 + tid;
            const int row = c >> 4, nc = (c & 15) << 3;
            __pipeline_memcpy_async(&Bs[row * BLD + nc],
                &Bm[(size_t)(k0 + row) * N + n0 + nc], 16);
        }
        __pipeline_commit();
    };

    const int NT = K / BK;
    issue(0); issue(1);

    const unsigned sbase = (unsigned)__cvta_generic_to_shared(hsm);
    const int aoff = (wm*32 + (lane & 15)) * ALD + (lane >> 4) * 8;  // +i*16*ALD +kk*16
    const int boff = lane * BLD + wn * 64;                            // +j*8

    for (int it = 0; it < NT; it++) {
        if (it + 2 < NT)      { issue(it + 2); __pipeline_wait_prior(2); }
        else if (it + 1 < NT) { __pipeline_wait_prior(1); }
        else                  { __pipeline_wait_prior(0); }
        __syncthreads();

        const unsigned sA = sbase + (unsigned)((it & 3) * ST_HALFS) * 2u;
        const unsigned sB = sA + (unsigned)(128*ALD) * 2u;

        // B fragments: one ldsm4t per n8 covers BOTH k16 halves (k rows = lanes).
        unsigned bf[8][4];
        #pragma unroll
        for (int j = 0; j < 8; j++)
            ldsm4t(bf[j], sB + (unsigned)(boff + j*8) * 2u);

        #pragma unroll
        for (int kk = 0; kk < 2; kk++) {
            unsigned af[2][4];
            ldsm4(af[0], sA + (unsigned)(aoff + kk*16) * 2u);
            ldsm4(af[1], sA + (unsigned)(aoff + 16*ALD + kk*16) * 2u);
            #pragma unroll
            for (int j = 0; j < 8; j++) {
                mma16816(acc[0][j], af[0], bf[j][2*kk], bf[j][2*kk+1]);
                mma16816(acc[1][j], af[1], bf[j][2*kk], bf[j][2*kk+1]);
            }
        }
    }

    // Direct register -> global epilogue (no smem staging).
    #pragma unroll
    for (int i = 0; i < 2; i++) {
        const int mr = m0 + wm*32 + i*16 + g;
        #pragma unroll
        for (int j = 0; j < 8; j++) {
            const int n = n0 + wn*64 + j*8 + 2*tg;
            const float b0 = bias[n], b1 = bias[n+1];
            const float v0 = acc[i][j][0] + b0, v1 = acc[i][j][1] + b1;
            const float v2 = acc[i][j][2] + b0, v3 = acc[i][j][3] + b1;
            if (MODE == 0) {
                float* C = (float*)Cout;
                *(float2*)&C[(size_t)mr * N + n]       = make_float2(v0, v1);
                *(float2*)&C[(size_t)(mr + 8) * N + n] = make_float2(v2, v3);
            } else {
                __half* C = (__half*)Cout;
                const int which = n >> 10, d = n & 1023;
                const int h = d >> 6, hd = d & 63;
                const int b_  = mr >> 11, s0 = mr & 2047;
                const int b2  = (mr + 8) >> 11, s2 = (mr + 8) & 2047;
                const size_t i0 =
                    ((((size_t)which * CB + b_) * CH + h) * CS + s0) * CHD + hd;
                const size_t i1 =
                    ((((size_t)which * CB + b2) * CH + h) * CS + s2) * CHD + hd;
                __half2 p0 = __floats2half2_rn(v0, v1);
                __half2 p1 = __floats2half2_rn(v2, v3);
                *(__half2*)&C[i0] = p0;
                *(__half2*)&C[i1] = p1;
            }
        }
    }
}

// ---------------------------------------------------------------------------
// Flash attention (R9, proven): raw mma, 128 q/CTA, 128-key super-tiles,
// packed-half2 ex2 softmax, ones-mma row sums, causal, single-pass.
// ---------------------------------------------------------------------------
#define HLD 72
#define KVT2 (128*HLD)
#define QTH (128*HLD)
#define ATTN_SMEM ((QTH + 4*KVT2) * 2)   // 92160 B
#define ONE2 0x3C003C00u

__global__ void __launch_bounds__(256, 2) attn_tc(
    const __half* __restrict__ qkv, __half* __restrict__ y)
{
    extern __shared__ __half smh[];
    __half* Qs = smh;
    __half* KV = smh + QTH;

    const int bh = blockIdx.y;
    const int qt = gridDim.x - 1 - blockIdx.x;
    const int t  = threadIdx.x;
    const int warp = t >> 5, lane = t & 31;
    const int rb = warp;
    const int g = lane >> 2, tg = lane & 3;

    const size_t hsz = (size_t)CS * CHD;
    const __half* Qg = qkv + (size_t)bh * hsz + (size_t)qt * 128 * 64;
    const __half* Kg = qkv + ((size_t)CBH + bh) * hsz;
    const __half* Vg = qkv + ((size_t)2*CBH + bh) * hsz;

    auto issueKV = [&](int st) {
        __half* Kd = KV + (st & 1) * 2 * KVT2;
        __half* Vd = Kd + KVT2;
        const __half* Ksrc = Kg + (size_t)st * 128 * 64;
        const __half* Vsrc = Vg + (size_t)st * 128 * 64;
        #pragma unroll
        for (int i = 0; i < 4; i++) {
            const int c = i * 256 + t;
            const int row = c >> 3, c8 = (c & 7) << 3;
            __pipeline_memcpy_async(&Kd[row*HLD + c8], &Ksrc[row*64 + c8], 16);
            __pipeline_memcpy_async(&Vd[row*HLD + c8], &Vsrc[row*64 + c8], 16);
        }
        __pipeline_commit();
    };

    const int nkt = qt + 1;

    #pragma unroll
    for (int i = 0; i < 4; i++) {
        const int c = i * 256 + t;
        const int row = c >> 3, c8 = (c & 7) << 3;
        __pipeline_memcpy_async(&Qs[row*HLD + c8], &Qg[row*64 + c8], 16);
    }
    issueKV(0);

    __pipeline_wait_prior(0);
    __syncthreads();

    unsigned qf[4][4];
    {
        const unsigned qb = (unsigned)__cvta_generic_to_shared(Qs);
        const int qrow = rb*16 + (lane & 15);
        const int qcoff = (lane >> 4) * 8;
        const __half2 qscale = __float2half2_rn(0.18033688f);  // log2(e)/8
        #pragma unroll
        for (int kc = 0; kc < 4; kc++) {
            ldsm4(qf[kc], qb + (unsigned)(qrow*HLD + kc*16 + qcoff) * 2u);
            #pragma unroll
            for (int j = 0; j < 4; j++) {
                __half2 v = *(__half2*)&qf[kc][j];
                v = __hmul2(v, qscale);
                qf[kc][j] = *(unsigned*)&v;
            }
        }
    }

    float yacc[8][4];
    #pragma unroll
    for (int i = 0; i < 8; i++)
        #pragma unroll
        for (int j = 0; j < 4; j++) yacc[i][j] = 0.f;
    float rsacc[4] = {0.f, 0.f, 0.f, 0.f};

    const unsigned kvb = (unsigned)__cvta_generic_to_shared(KV);
    const int krow  = ((lane >> 4) << 3) + (lane & 7);
    const int kcoff = ((lane >> 3) & 1) * 8;
    const int row0  = rb*16 + g;
    const int qabs0 = qt*128 + row0;

    for (int st = 0; st < nkt; st++) {
        if (st > 0) {
            __pipeline_wait_prior(0);
            __syncthreads();
        }
        if (st + 1 < nkt) issueKV(st + 1);

        const unsigned KsB = kvb + (unsigned)((st & 1) * 2 * KVT2) * 2u;
        const unsigned VsB = KsB + (unsigned)KVT2 * 2u;
        const bool diag = (st == nkt - 1);

        #pragma unroll
        for (int sub = 0; sub < 2; sub++) {
            if (diag && sub == 1 && rb < 4) break;

            const unsigned Kb32 = KsB + (unsigned)(sub * 64 * HLD) * 2u;
            const unsigned Vb32 = VsB + (unsigned)(sub * 64 * HLD) * 2u;

            float sacc[8][4];
            #pragma unroll
            for (int i = 0; i < 8; i++)
                #pragma unroll
                for (int j = 0; j < 4; j++) sacc[i][j] = 0.f;

            #pragma unroll
            for (int kc = 0; kc < 4; kc++) {
                const unsigned cb = (unsigned)(kc*16 + kcoff) * 2u;
                #pragma unroll
                for (int kb = 0; kb < 4; kb++) {
                    unsigned kf[4];
                    ldsm4(kf, Kb32 + (unsigned)((krow + kb*16)*HLD)*2u + cb);
                    mma16816(sacc[kb*2],     qf[kc], kf[0], kf[1]);
                    mma16816(sacc[kb*2 + 1], qf[kc], kf[2], kf[3]);
                }
            }

            if (diag) {
                const int kbase = st*128 + sub*64;
                #pragma unroll
                for (int nb = 0; nb < 8; nb++) {
                    const int cb = kbase + nb*8 + 2*tg;
                    if (cb     > qabs0    ) sacc[nb][0] = -30000.f;
                    if (cb + 1 > qabs0    ) sacc[nb][1] = -30000.f;
                    if (cb     > qabs0 + 8) sacc[nb][2] = -30000.f;
                    if (cb + 1 > qabs0 + 8) sacc[nb][3] = -30000.f;
                }
            }

            unsigned pf[4][4];
            #pragma unroll
            for (int c = 0; c < 4; c++) {
                pf[c][0] = hex2(h2pack(sacc[2*c][0],     sacc[2*c][1]));
                pf[c][1] = hex2(h2pack(sacc[2*c][2],     sacc[2*c][3]));
                pf[c][2] = hex2(h2pack(sacc[2*c + 1][0], sacc[2*c + 1][1]));
                pf[c][3] = hex2(h2pack(sacc[2*c + 1][2], sacc[2*c + 1][3]));
            }

            #pragma unroll
            for (int c = 0; c < 4; c++)
                mma16816(rsacc, pf[c], ONE2, ONE2);

            #pragma unroll
            for (int nd = 0; nd < 8; nd++) {
                unsigned vfA[4], vfB[4];
                ldsm4t(vfA, Vb32 + (unsigned)( lane      *HLD + nd*8) * 2u);
                ldsm4t(vfB, Vb32 + (unsigned)((lane + 32)*HLD + nd*8) * 2u);
                mma16816(yacc[nd], pf[0], vfA[0], vfA[1]);
                mma16816(yacc[nd], pf[1], vfA[2], vfA[3]);
                mma16816(yacc[nd], pf[2], vfB[0], vfB[1]);
                mma16816(yacc[nd], pf[3], vfB[2], vfB[3]);
            }
        }
    }

    const float inv0 = 1.f / rsacc[0];
    const float inv1 = 1.f / rsacc[2];

    const int b = bh >> 4, h = bh & 15;
    const int q0 = qt*128 + row0;
    __half* yo0 = y + ((size_t)(b * CS + q0)) * CD + h*64;
    __half* yo1 = yo0 + (size_t)8 * CD;
    #pragma unroll
    for (int nd = 0; nd < 8; nd++) {
        const int col = nd*8 + 2*tg;
        __half2 h0 = __floats2half2_rn(yacc[nd][0]*inv0, yacc[nd][1]*inv0);
        __half2 h1 = __floats2half2_rn(yacc[nd][2]*inv1, yacc[nd][3]*inv1);
        *(__half2*)&yo0[col] = h0;
        *(__half2*)&yo1[col] = h1;
    }
}

// ---------------------------------------------------------------------------
extern "C" void kernel_launch(void* const* d_in, const int* in_sizes, int n_in,
                              void* d_out, int out_size)
{
    const float* x  = (const float*)d_in[0];
    const float* Wa = (const float*)d_in[1];
    const float* ba = (const float*)d_in[2];
    const float* Wp = (const float*)d_in[3];
    const float* bp = (const float*)d_in[4];
    float* out = (float*)d_out;

    __half *qkv, *y, *xh, *wa, *wp;
    cudaGetSymbolAddress((void**)&qkv, g_qkv);
    cudaGetSymbolAddress((void**)&y,   g_y);
    cudaGetSymbolAddress((void**)&xh,  g_xh);
    cudaGetSymbolAddress((void**)&wa,  g_wa);
    cudaGetSymbolAddress((void**)&wp,  g_wp);

    cudaFuncSetAttribute(gemm_r<0>,
        cudaFuncAttributeMaxDynamicSharedMemorySize, GEMM_SMEM);
    cudaFuncSetAttribute(gemm_r<1>,
        cudaFuncAttributeMaxDynamicSharedMemorySize, GEMM_SMEM);
    cudaFuncSetAttribute(attn_tc,
        cudaFuncAttributeMaxDynamicSharedMemorySize, ATTN_SMEM);

    const int ncv = N4_X + N4_WA + N4_WP;
    cvt_all_kernel<<<(ncv + 255)/256, 256>>>(x, Wa, Wp, xh, wa, wp);

    gemm_r<1><<<dim3(3*CD/128, CB*CS/128), 256, GEMM_SMEM>>>(
        xh, wa, ba, qkv, CB*CS, 3*CD, CD);
    attn_tc<<<dim3(CS/128, CBH), 256, ATTN_SMEM>>>(qkv, y);
    gemm_r<0><<<dim3(CD/128, CB*CS/128), 256, GEMM_SMEM>>>(
        y, wp, bp, out, CB*CS, CD, CD);
}

// round 13
// speedup vs baseline: 1.0509x; 1.0509x over previous
#include <cuda_runtime.h>
#include <cuda_fp16.h>
#include <cuda_pipeline.h>
#include <mma.h>
using namespace nvcuda;

// Problem constants
#define CB 4
#define CS 2048
#define CD 1024
#define CH 16
#define CHD 64
#define CBH (CB*CH)

// Scratch (allocation-free)
__device__ __align__(16) __half g_qkv[(size_t)3*CBH*CS*CHD]; // [3][BH][S][HD]
__device__ __align__(16) __half g_y [(size_t)CB*CS*CD];      // [B][S][D]
__device__ __align__(16) __half g_xh[(size_t)CB*CS*CD];
__device__ __align__(16) __half g_wa[(size_t)CD*3*CD];
__device__ __align__(16) __half g_wp[(size_t)CD*CD];

// ---------------------------------------------------------------------------
// One fused fp32 -> fp16 conversion pass over x, Wa, Wp.
// ---------------------------------------------------------------------------
#define N4_X  (CB*CS*CD/4)
#define N4_WA (3*CD*CD/4)
#define N4_WP (CD*CD/4)

__global__ void cvt_all_kernel(const float* __restrict__ x,
                               const float* __restrict__ Wa,
                               const float* __restrict__ Wp,
                               __half* __restrict__ xh,
                               __half* __restrict__ wa,
                               __half* __restrict__ wp)
{
    const int i = blockIdx.x * blockDim.x + threadIdx.x;
    const float4* src;
    __half* dst;
    int j = i;
    if (i < N4_X)                      { src = (const float4*)x;  dst = xh; }
    else if (i < N4_X + N4_WA)         { src = (const float4*)Wa; dst = wa; j = i - N4_X; }
    else if (i < N4_X + N4_WA + N4_WP) { src = (const float4*)Wp; dst = wp; j = i - N4_X - N4_WA; }
    else return;
    float4 v = src[j];
    __half2 lo = __floats2half2_rn(v.x, v.y);
    __half2 hi = __floats2half2_rn(v.z, v.w);
    uint2 u;
    u.x = *(unsigned int*)&lo;
    u.y = *(unsigned int*)&hi;
    ((uint2*)dst)[j] = u;
}

// ---------------------------------------------------------------------------
// FP16 wmma GEMM, cp.async 4-stage, BK=32 (R9 proven config).
// ---------------------------------------------------------------------------
#define BK 32
#define ALD 40
#define BLD 136
#define ST_HALFS (128*ALD + BK*BLD)
#define GEMM_SMEM (4*ST_HALFS*2)

template<int MODE>
__global__ void __launch_bounds__(256, 2) gemm_h(
    const __half* __restrict__ A, const __half* __restrict__ Bm,
    const float* __restrict__ bias, void* __restrict__ Cout,
    int M, int N, int K)
{
    extern __shared__ __half hsm[];
    const int tid = threadIdx.x;
    const int warp = tid >> 5;
    const int wm = warp & 3, wn = warp >> 2;
    const int m0 = blockIdx.y * 128, n0 = blockIdx.x * 128;

    wmma::fragment<wmma::accumulator,16,16,16,float> cf[2][4];
    #pragma unroll
    for (int i = 0; i < 2; i++)
        #pragma unroll
        for (int j = 0; j < 4; j++) wmma::fill_fragment(cf[i][j], 0.f);

    auto issue = [&](int it) {
        __half* As = hsm + (it & 3) * ST_HALFS;
        __half* Bs = As + 128*ALD;
        const int k0 = it * BK;
        #pragma unroll
        for (int i = 0; i < 2; i++) {
            const int c = i * 256 + tid;
            const int row = c >> 2, kc = (c & 3) << 3;
            __pipeline_memcpy_async(&As[row * ALD + kc],
                &A[(size_t)(m0 + row) * K + k0 + kc], 16);
        }
        #pragma unroll
        for (int i = 0; i < 2; i++) {
            const int c = i * 256 + tid;
            const int row = c >> 4, nc = (c & 15) << 3;
            __pipeline_memcpy_async(&Bs[row * BLD + nc],
                &Bm[(size_t)(k0 + row) * N + n0 + nc], 16);
        }
        __pipeline_commit();
    };

    const int NT = K / BK;
    issue(0); issue(1);

    for (int it = 0; it < NT; it++) {
        if (it + 2 < NT)      { issue(it + 2); __pipeline_wait_prior(2); }
        else if (it + 1 < NT) { __pipeline_wait_prior(1); }
        else                  { __pipeline_wait_prior(0); }
        __syncthreads();

        const __half* As = hsm + (it & 3) * ST_HALFS;
        const __half* Bs = As + 128*ALD;
        #pragma unroll
        for (int kk = 0; kk < 2; kk++) {
            wmma::fragment<wmma::matrix_a,16,16,16,__half,wmma::row_major> af[2];
            #pragma unroll
            for (int i = 0; i < 2; i++)
                wmma::load_matrix_sync(af[i], &As[(wm*32 + i*16) * ALD + kk*16], ALD);
            #pragma unroll
            for (int j = 0; j < 4; j++) {
                wmma::fragment<wmma::matrix_b,16,16,16,__half,wmma::row_major> bf;
                wmma::load_matrix_sync(bf, &Bs[(kk*16) * BLD + wn*64 + j*16], BLD);
                #pragma unroll
                for (int i = 0; i < 2; i++)
                    wmma::mma_sync(cf[i][j], af[i], bf, cf[i][j]);
            }
        }
    }
    __syncthreads();

    float* Csm = (float*)hsm;
    #pragma unroll
    for (int i = 0; i < 2; i++)
        #pragma unroll
        for (int j = 0; j < 4; j++)
            wmma::store_matrix_sync(&Csm[(wm*32 + i*16) * 132 + wn*64 + j*16],
                                    cf[i][j], 132, wmma::mem_row_major);
    __syncthreads();

    #pragma unroll
    for (int itc = 0; itc < 16; itc++) {
        const int idx4 = itc * 256 + tid;
        const int row = idx4 >> 5;
        const int c4  = (idx4 & 31) << 2;
        float4 v = *(float4*)&Csm[row * 132 + c4];
        const int n = n0 + c4;
        v.x += bias[n]; v.y += bias[n+1]; v.z += bias[n+2]; v.w += bias[n+3];
        const int m = m0 + row;
        if (MODE == 0) {
            *(float4*)&((float*)Cout)[(size_t)m * N + n] = v;
        } else {
            __half2 p0 = __floats2half2_rn(v.x, v.y);
            __half2 p1 = __floats2half2_rn(v.z, v.w);
            uint2 u; u.x = *(unsigned int*)&p0; u.y = *(unsigned int*)&p1;
            const int which = n >> 10, d = n & 1023;
            const int h = d >> 6, hd = d & 63;
            const int b = m >> 11, s = m & 2047;
            const size_t idx =
                ((((size_t)which * CB + b) * CH + h) * CS + s) * CHD + hd;
            *(uint2*)&((__half*)Cout)[idx] = u;
        }
    }
}

// ---------------------------------------------------------------------------
// Raw-mma helpers
// ---------------------------------------------------------------------------
__device__ __forceinline__ void ldsm4(unsigned* d, unsigned a) {
    asm volatile("ldmatrix.sync.aligned.m8n8.x4.shared.b16 {%0,%1,%2,%3}, [%4];"
        : "=r"(d[0]), "=r"(d[1]), "=r"(d[2]), "=r"(d[3]) : "r"(a));
}
__device__ __forceinline__ void ldsm4t(unsigned* d, unsigned a) {
    asm volatile("ldmatrix.sync.aligned.m8n8.x4.trans.shared.b16 {%0,%1,%2,%3}, [%4];"
        : "=r"(d[0]), "=r"(d[1]), "=r"(d[2]), "=r"(d[3]) : "r"(a));
}
__device__ __forceinline__ void mma16816(float* c, const unsigned* a,
                                         unsigned b0, unsigned b1) {
    asm volatile(
        "mma.sync.aligned.m16n8k16.row.col.f32.f16.f16.f32 "
        "{%0,%1,%2,%3}, {%4,%5,%6,%7}, {%8,%9}, {%0,%1,%2,%3};"
        : "+f"(c[0]), "+f"(c[1]), "+f"(c[2]), "+f"(c[3])
        : "r"(a[0]), "r"(a[1]), "r"(a[2]), "r"(a[3]), "r"(b0), "r"(b1));
}
__device__ __forceinline__ unsigned h2pack(float a, float b) {
    __half2 h = __floats2half2_rn(a, b);
    return *(unsigned*)&h;
}
__device__ __forceinline__ unsigned hex2(unsigned x) {   // 2^x on packed half2
    unsigned d;
    asm("ex2.approx.f16x2 %0, %1;" : "=r"(d) : "r"(x));
    return d;
}

// ---------------------------------------------------------------------------
// Flash attention: raw mma, 128 q/CTA, 128-key super-tiles, packed-half2 ex2
// softmax, causal, single-pass.  Row sums on the ALU pipe via HADD2 tree.
// A-fragment register layout: pf[c][0],pf[c][2] -> row g;
//                             pf[c][1],pf[c][3] -> row g+8.   (R11 bug fixed)
// ---------------------------------------------------------------------------
#define HLD 72
#define KVT2 (128*HLD)
#define QTH (128*HLD)
#define ATTN_SMEM ((QTH + 4*KVT2) * 2)   // 92160 B

__global__ void __launch_bounds__(256, 2) attn_tc(
    const __half* __restrict__ qkv, __half* __restrict__ y)
{
    extern __shared__ __half smh[];
    __half* Qs = smh;
    __half* KV = smh + QTH;

    const int bh = blockIdx.y;
    const int qt = gridDim.x - 1 - blockIdx.x;
    const int t  = threadIdx.x;
    const int warp = t >> 5, lane = t & 31;
    const int rb = warp;
    const int g = lane >> 2, tg = lane & 3;

    const size_t hsz = (size_t)CS * CHD;
    const __half* Qg = qkv + (size_t)bh * hsz + (size_t)qt * 128 * 64;
    const __half* Kg = qkv + ((size_t)CBH + bh) * hsz;
    const __half* Vg = qkv + ((size_t)2*CBH + bh) * hsz;

    auto issueKV = [&](int st) {
        __half* Kd = KV + (st & 1) * 2 * KVT2;
        __half* Vd = Kd + KVT2;
        const __half* Ksrc = Kg + (size_t)st * 128 * 64;
        const __half* Vsrc = Vg + (size_t)st * 128 * 64;
        #pragma unroll
        for (int i = 0; i < 4; i++) {
            const int c = i * 256 + t;
            const int row = c >> 3, c8 = (c & 7) << 3;
            __pipeline_memcpy_async(&Kd[row*HLD + c8], &Ksrc[row*64 + c8], 16);
            __pipeline_memcpy_async(&Vd[row*HLD + c8], &Vsrc[row*64 + c8], 16);
        }
        __pipeline_commit();
    };

    const int nkt = qt + 1;

    #pragma unroll
    for (int i = 0; i < 4; i++) {
        const int c = i * 256 + t;
        const int row = c >> 3, c8 = (c & 7) << 3;
        __pipeline_memcpy_async(&Qs[row*HLD + c8], &Qg[row*64 + c8], 16);
    }
    issueKV(0);

    __pipeline_wait_prior(0);
    __syncthreads();

    unsigned qf[4][4];
    {
        const unsigned qb = (unsigned)__cvta_generic_to_shared(Qs);
        const int qrow = rb*16 + (lane & 15);
        const int qcoff = (lane >> 4) * 8;
        const __half2 qscale = __float2half2_rn(0.18033688f);  // log2(e)/8
        #pragma unroll
        for (int kc = 0; kc < 4; kc++) {
            ldsm4(qf[kc], qb + (unsigned)(qrow*HLD + kc*16 + qcoff) * 2u);
            #pragma unroll
            for (int j = 0; j < 4; j++) {
                __half2 v = *(__half2*)&qf[kc][j];
                v = __hmul2(v, qscale);
                qf[kc][j] = *(unsigned*)&v;
            }
        }
    }

    float yacc[8][4];
    #pragma unroll
    for (int i = 0; i < 8; i++)
        #pragma unroll
        for (int j = 0; j < 4; j++) yacc[i][j] = 0.f;
    float rs0 = 0.f, rs1 = 0.f;   // fp32 across subtiles

    const unsigned kvb = (unsigned)__cvta_generic_to_shared(KV);
    const int krow  = ((lane >> 4) << 3) + (lane & 7);
    const int kcoff = ((lane >> 3) & 1) * 8;
    const int row0  = rb*16 + g;
    const int qabs0 = qt*128 + row0;

    for (int st = 0; st < nkt; st++) {
        if (st > 0) {
            __pipeline_wait_prior(0);
            __syncthreads();
        }
        if (st + 1 < nkt) issueKV(st + 1);

        const unsigned KsB = kvb + (unsigned)((st & 1) * 2 * KVT2) * 2u;
        const unsigned VsB = KsB + (unsigned)KVT2 * 2u;
        const bool diag = (st == nkt - 1);

        #pragma unroll
        for (int sub = 0; sub < 2; sub++) {
            if (diag && sub == 1 && rb < 4) break;

            const unsigned Kb32 = KsB + (unsigned)(sub * 64 * HLD) * 2u;
            const unsigned Vb32 = VsB + (unsigned)(sub * 64 * HLD) * 2u;

            float sacc[8][4];
            #pragma unroll
            for (int i = 0; i < 8; i++)
                #pragma unroll
                for (int j = 0; j < 4; j++) sacc[i][j] = 0.f;

            #pragma unroll
            for (int kc = 0; kc < 4; kc++) {
                const unsigned cb = (unsigned)(kc*16 + kcoff) * 2u;
                #pragma unroll
                for (int kb = 0; kb < 4; kb++) {
                    unsigned kf[4];
                    ldsm4(kf, Kb32 + (unsigned)((krow + kb*16)*HLD)*2u + cb);
                    mma16816(sacc[kb*2],     qf[kc], kf[0], kf[1]);
                    mma16816(sacc[kb*2 + 1], qf[kc], kf[2], kf[3]);
                }
            }

            if (diag) {
                const int kbase = st*128 + sub*64;
                #pragma unroll
                for (int nb = 0; nb < 8; nb++) {
                    const int cb = kbase + nb*8 + 2*tg;
                    if (cb     > qabs0    ) sacc[nb][0] = -30000.f;
                    if (cb + 1 > qabs0    ) sacc[nb][1] = -30000.f;
                    if (cb     > qabs0 + 8) sacc[nb][2] = -30000.f;
                    if (cb + 1 > qabs0 + 8) sacc[nb][3] = -30000.f;
                }
            }

            unsigned pf[4][4];
            #pragma unroll
            for (int c = 0; c < 4; c++) {
                pf[c][0] = hex2(h2pack(sacc[2*c][0],     sacc[2*c][1]));
                pf[c][1] = hex2(h2pack(sacc[2*c][2],     sacc[2*c][3]));
                pf[c][2] = hex2(h2pack(sacc[2*c + 1][0], sacc[2*c + 1][1]));
                pf[c][3] = hex2(h2pack(sacc[2*c + 1][2], sacc[2*c + 1][3]));
            }

            // Row sums (ALU pipe). A-frag layout: regs {0,2} = row g -> rs0,
            // regs {1,3} = row g+8 -> rs1. Partial <= 16 in half: safe.
            {
                __half2 a0 = __hadd2(__hadd2(*(__half2*)&pf[0][0], *(__half2*)&pf[0][2]),
                                     __hadd2(*(__half2*)&pf[1][0], *(__half2*)&pf[1][2]));
                __half2 a1 = __hadd2(__hadd2(*(__half2*)&pf[2][0], *(__half2*)&pf[2][2]),
                                     __hadd2(*(__half2*)&pf[3][0], *(__half2*)&pf[3][2]));
                __half2 s0 = __hadd2(a0, a1);
                rs0 += __low2float(s0) + __high2float(s0);

                __half2 b0 = __hadd2(__hadd2(*(__half2*)&pf[0][1], *(__half2*)&pf[0][3]),
                                     __hadd2(*(__half2*)&pf[1][1], *(__half2*)&pf[1][3]));
                __half2 b1 = __hadd2(__hadd2(*(__half2*)&pf[2][1], *(__half2*)&pf[2][3]),
                                     __hadd2(*(__half2*)&pf[3][1], *(__half2*)&pf[3][3]));
                __half2 s1 = __hadd2(b0, b1);
                rs1 += __low2float(s1) + __high2float(s1);
            }

            #pragma unroll
            for (int nd = 0; nd < 8; nd++) {
                unsigned vfA[4], vfB[4];
                ldsm4t(vfA, Vb32 + (unsigned)( lane      *HLD + nd*8) * 2u);
                ldsm4t(vfB, Vb32 + (unsigned)((lane + 32)*HLD + nd*8) * 2u);
                mma16816(yacc[nd], pf[0], vfA[0], vfA[1]);
                mma16816(yacc[nd], pf[1], vfA[2], vfA[3]);
                mma16816(yacc[nd], pf[2], vfB[0], vfB[1]);
                mma16816(yacc[nd], pf[3], vfB[2], vfB[3]);
            }
        }
    }

    // Complete row sums across the 4 quad lanes.
    rs0 += __shfl_xor_sync(0xffffffffu, rs0, 1);
    rs0 += __shfl_xor_sync(0xffffffffu, rs0, 2);
    rs1 += __shfl_xor_sync(0xffffffffu, rs1, 1);
    rs1 += __shfl_xor_sync(0xffffffffu, rs1, 2);
    const float inv0 = 1.f / rs0;
    const float inv1 = 1.f / rs1;

    const int b = bh >> 4, h = bh & 15;
    const int q0 = qt*128 + row0;
    __half* yo0 = y + ((size_t)(b * CS + q0)) * CD + h*64;
    __half* yo1 = yo0 + (size_t)8 * CD;
    #pragma unroll
    for (int nd = 0; nd < 8; nd++) {
        const int col = nd*8 + 2*tg;
        __half2 h0 = __floats2half2_rn(yacc[nd][0]*inv0, yacc[nd][1]*inv0);
        __half2 h1 = __floats2half2_rn(yacc[nd][2]*inv1, yacc[nd][3]*inv1);
        *(__half2*)&yo0[col] = h0;
        *(__half2*)&yo1[col] = h1;
    }
}

// ---------------------------------------------------------------------------
extern "C" void kernel_launch(void* const* d_in, const int* in_sizes, int n_in,
                              void* d_out, int out_size)
{
    const float* x  = (const float*)d_in[0];
    const float* Wa = (const float*)d_in[1];
    const float* ba = (const float*)d_in[2];
    const float* Wp = (const float*)d_in[3];
    const float* bp = (const float*)d_in[4];
    float* out = (float*)d_out;

    __half *qkv, *y, *xh, *wa, *wp;
    cudaGetSymbolAddress((void**)&qkv, g_qkv);
    cudaGetSymbolAddress((void**)&y,   g_y);
    cudaGetSymbolAddress((void**)&xh,  g_xh);
    cudaGetSymbolAddress((void**)&wa,  g_wa);
    cudaGetSymbolAddress((void**)&wp,  g_wp);

    cudaFuncSetAttribute(gemm_h<0>,
        cudaFuncAttributeMaxDynamicSharedMemorySize, GEMM_SMEM);
    cudaFuncSetAttribute(gemm_h<1>,
        cudaFuncAttributeMaxDynamicSharedMemorySize, GEMM_SMEM);
    cudaFuncSetAttribute(attn_tc,
        cudaFuncAttributeMaxDynamicSharedMemorySize, ATTN_SMEM);

    const int ncv = N4_X + N4_WA + N4_WP;
    cvt_all_kernel<<<(ncv + 255)/256, 256>>>(x, Wa, Wp, xh, wa, wp);

    gemm_h<1><<<dim3(3*CD/128, CB*CS/128), 256, GEMM_SMEM>>>(
        xh, wa, ba, qkv, CB*CS, 3*CD, CD);
    attn_tc<<<dim3(CS/128, CBH), 256, ATTN_SMEM>>>(qkv, y);
    gemm_h<0><<<dim3(CD/128, CB*CS/128), 256, GEMM_SMEM>>>(
        y, wp, bp, out, CB*CS, CD, CD);
}

// round 14
// speedup vs baseline: 1.0607x; 1.0093x over previous
#include <cuda_runtime.h>
#include <cuda_fp16.h>
#include <cuda_pipeline.h>
#include <mma.h>
using namespace nvcuda;

// Problem constants
#define CB 4
#define CS 2048
#define CD 1024
#define CH 16
#define CHD 64
#define CBH (CB*CH)

// Scratch (allocation-free)
__device__ __align__(16) __half g_qkv[(size_t)3*CBH*CS*CHD]; // [3][BH][S][HD]
__device__ __align__(16) __half g_y [(size_t)CB*CS*CD];      // [B][S][D]
__device__ __align__(16) __half g_xh[(size_t)CB*CS*CD];
__device__ __align__(16) __half g_wa[(size_t)CD*3*CD];
__device__ __align__(16) __half g_wp[(size_t)CD*CD];

// ---------------------------------------------------------------------------
// One fused fp32 -> fp16 conversion pass over x, Wa, Wp.
// ---------------------------------------------------------------------------
#define N4_X  (CB*CS*CD/4)
#define N4_WA (3*CD*CD/4)
#define N4_WP (CD*CD/4)

__global__ void cvt_all_kernel(const float* __restrict__ x,
                               const float* __restrict__ Wa,
                               const float* __restrict__ Wp,
                               __half* __restrict__ xh,
                               __half* __restrict__ wa,
                               __half* __restrict__ wp)
{
    const int i = blockIdx.x * blockDim.x + threadIdx.x;
    const float4* src;
    __half* dst;
    int j = i;
    if (i < N4_X)                      { src = (const float4*)x;  dst = xh; }
    else if (i < N4_X + N4_WA)         { src = (const float4*)Wa; dst = wa; j = i - N4_X; }
    else if (i < N4_X + N4_WA + N4_WP) { src = (const float4*)Wp; dst = wp; j = i - N4_X - N4_WA; }
    else return;
    float4 v = src[j];
    __half2 lo = __floats2half2_rn(v.x, v.y);
    __half2 hi = __floats2half2_rn(v.z, v.w);
    uint2 u;
    u.x = *(unsigned int*)&lo;
    u.y = *(unsigned int*)&hi;
    ((uint2*)dst)[j] = u;
}

// ---------------------------------------------------------------------------
// FP16 wmma GEMM, cp.async 4-stage, BK=32 (proven config; f32 accumulate).
// ---------------------------------------------------------------------------
#define BK 32
#define ALD 40
#define BLD 136
#define ST_HALFS (128*ALD + BK*BLD)
#define GEMM_SMEM (4*ST_HALFS*2)

template<int MODE>
__global__ void __launch_bounds__(256, 2) gemm_h(
    const __half* __restrict__ A, const __half* __restrict__ Bm,
    const float* __restrict__ bias, void* __restrict__ Cout,
    int M, int N, int K)
{
    extern __shared__ __half hsm[];
    const int tid = threadIdx.x;
    const int warp = tid >> 5;
    const int wm = warp & 3, wn = warp >> 2;
    const int m0 = blockIdx.y * 128, n0 = blockIdx.x * 128;

    wmma::fragment<wmma::accumulator,16,16,16,float> cf[2][4];
    #pragma unroll
    for (int i = 0; i < 2; i++)
        #pragma unroll
        for (int j = 0; j < 4; j++) wmma::fill_fragment(cf[i][j], 0.f);

    auto issue = [&](int it) {
        __half* As = hsm + (it & 3) * ST_HALFS;
        __half* Bs = As + 128*ALD;
        const int k0 = it * BK;
        #pragma unroll
        for (int i = 0; i < 2; i++) {
            const int c = i * 256 + tid;
            const int row = c >> 2, kc = (c & 3) << 3;
            __pipeline_memcpy_async(&As[row * ALD + kc],
                &A[(size_t)(m0 + row) * K + k0 + kc], 16);
        }
        #pragma unroll
        for (int i = 0; i < 2; i++) {
            const int c = i * 256 + tid;
            const int row = c >> 4, nc = (c & 15) << 3;
            __pipeline_memcpy_async(&Bs[row * BLD + nc],
                &Bm[(size_t)(k0 + row) * N + n0 + nc], 16);
        }
        __pipeline_commit();
    };

    const int NT = K / BK;
    issue(0); issue(1);

    for (int it = 0; it < NT; it++) {
        if (it + 2 < NT)      { issue(it + 2); __pipeline_wait_prior(2); }
        else if (it + 1 < NT) { __pipeline_wait_prior(1); }
        else                  { __pipeline_wait_prior(0); }
        __syncthreads();

        const __half* As = hsm + (it & 3) * ST_HALFS;
        const __half* Bs = As + 128*ALD;
        #pragma unroll
        for (int kk = 0; kk < 2; kk++) {
            wmma::fragment<wmma::matrix_a,16,16,16,__half,wmma::row_major> af[2];
            #pragma unroll
            for (int i = 0; i < 2; i++)
                wmma::load_matrix_sync(af[i], &As[(wm*32 + i*16) * ALD + kk*16], ALD);
            #pragma unroll
            for (int j = 0; j < 4; j++) {
                wmma::fragment<wmma::matrix_b,16,16,16,__half,wmma::row_major> bf;
                wmma::load_matrix_sync(bf, &Bs[(kk*16) * BLD + wn*64 + j*16], BLD);
                #pragma unroll
                for (int i = 0; i < 2; i++)
                    wmma::mma_sync(cf[i][j], af[i], bf, cf[i][j]);
            }
        }
    }
    __syncthreads();

    float* Csm = (float*)hsm;
    #pragma unroll
    for (int i = 0; i < 2; i++)
        #pragma unroll
        for (int j = 0; j < 4; j++)
            wmma::store_matrix_sync(&Csm[(wm*32 + i*16) * 132 + wn*64 + j*16],
                                    cf[i][j], 132, wmma::mem_row_major);
    __syncthreads();

    #pragma unroll
    for (int itc = 0; itc < 16; itc++) {
        const int idx4 = itc * 256 + tid;
        const int row = idx4 >> 5;
        const int c4  = (idx4 & 31) << 2;
        float4 v = *(float4*)&Csm[row * 132 + c4];
        const int n = n0 + c4;
        v.x += bias[n]; v.y += bias[n+1]; v.z += bias[n+2]; v.w += bias[n+3];
        const int m = m0 + row;
        if (MODE == 0) {
            *(float4*)&((float*)Cout)[(size_t)m * N + n] = v;
        } else {
            __half2 p0 = __floats2half2_rn(v.x, v.y);
            __half2 p1 = __floats2half2_rn(v.z, v.w);
            uint2 u; u.x = *(unsigned int*)&p0; u.y = *(unsigned int*)&p1;
            const int which = n >> 10, d = n & 1023;
            const int h = d >> 6, hd = d & 63;
            const int b = m >> 11, s = m & 2047;
            const size_t idx =
                ((((size_t)which * CB + b) * CH + h) * CS + s) * CHD + hd;
            *(uint2*)&((__half*)Cout)[idx] = u;
        }
    }
}

// ---------------------------------------------------------------------------
// Raw-mma helpers
// ---------------------------------------------------------------------------
__device__ __forceinline__ void ldsm4(unsigned* d, unsigned a) {
    asm volatile("ldmatrix.sync.aligned.m8n8.x4.shared.b16 {%0,%1,%2,%3}, [%4];"
        : "=r"(d[0]), "=r"(d[1]), "=r"(d[2]), "=r"(d[3]) : "r"(a));
}
__device__ __forceinline__ void ldsm4t(unsigned* d, unsigned a) {
    asm volatile("ldmatrix.sync.aligned.m8n8.x4.trans.shared.b16 {%0,%1,%2,%3}, [%4];"
        : "=r"(d[0]), "=r"(d[1]), "=r"(d[2]), "=r"(d[3]) : "r"(a));
}
// f32-accumulate (PV)
__device__ __forceinline__ void mma16816(float* c, const unsigned* a,
                                         unsigned b0, unsigned b1) {
    asm volatile(
        "mma.sync.aligned.m16n8k16.row.col.f32.f16.f16.f32 "
        "{%0,%1,%2,%3}, {%4,%5,%6,%7}, {%8,%9}, {%0,%1,%2,%3};"
        : "+f"(c[0]), "+f"(c[1]), "+f"(c[2]), "+f"(c[3])
        : "r"(a[0]), "r"(a[1]), "r"(a[2]), "r"(a[3]), "r"(b0), "r"(b1));
}
// f16-accumulate (QK^T — K=64 only, safe). Acc regs: c0=(row g, cols 2tg..),
// c1=(row g+8, cols 2tg..) — already the packed P A-fragment layout.
__device__ __forceinline__ void mma16816h(unsigned* c, const unsigned* a,
                                          unsigned b0, unsigned b1) {
    asm volatile(
        "mma.sync.aligned.m16n8k16.row.col.f16.f16.f16.f16 "
        "{%0,%1}, {%2,%3,%4,%5}, {%6,%7}, {%0,%1};"
        : "+r"(c[0]), "+r"(c[1])
        : "r"(a[0]), "r"(a[1]), "r"(a[2]), "r"(a[3]), "r"(b0), "r"(b1));
}
__device__ __forceinline__ unsigned hex2(unsigned x) {   // 2^x on packed half2
    unsigned d;
    asm("ex2.approx.f16x2 %0, %1;" : "=r"(d) : "r"(x));
    return d;
}

// ---------------------------------------------------------------------------
// Flash attention: raw mma, 128 q/CTA, 128-key super-tiles, causal,
// single-pass.  QK^T now accumulates in FP16 (layout == P fragment: no
// repack cvts); P = ex2.f16x2 directly on accumulator regs; masking via
// HADD2 of -30000 on the diagonal tile; rowsums on ALU pipe.
// ---------------------------------------------------------------------------
#define HLD 72
#define KVT2 (128*HLD)
#define QTH (128*HLD)
#define ATTN_SMEM ((QTH + 4*KVT2) * 2)   // 92160 B

__global__ void __launch_bounds__(256, 2) attn_tc(
    const __half* __restrict__ qkv, __half* __restrict__ y)
{
    extern __shared__ __half smh[];
    __half* Qs = smh;
    __half* KV = smh + QTH;

    const int bh = blockIdx.y;
    const int qt = gridDim.x - 1 - blockIdx.x;
    const int t  = threadIdx.x;
    const int warp = t >> 5, lane = t & 31;
    const int rb = warp;
    const int g = lane >> 2, tg = lane & 3;

    const size_t hsz = (size_t)CS * CHD;
    const __half* Qg = qkv + (size_t)bh * hsz + (size_t)qt * 128 * 64;
    const __half* Kg = qkv + ((size_t)CBH + bh) * hsz;
    const __half* Vg = qkv + ((size_t)2*CBH + bh) * hsz;

    auto issueKV = [&](int st) {
        __half* Kd = KV + (st & 1) * 2 * KVT2;
        __half* Vd = Kd + KVT2;
        const __half* Ksrc = Kg + (size_t)st * 128 * 64;
        const __half* Vsrc = Vg + (size_t)st * 128 * 64;
        #pragma unroll
        for (int i = 0; i < 4; i++) {
            const int c = i * 256 + t;
            const int row = c >> 3, c8 = (c & 7) << 3;
            __pipeline_memcpy_async(&Kd[row*HLD + c8], &Ksrc[row*64 + c8], 16);
            __pipeline_memcpy_async(&Vd[row*HLD + c8], &Vsrc[row*64 + c8], 16);
        }
        __pipeline_commit();
    };

    const int nkt = qt + 1;

    #pragma unroll
    for (int i = 0; i < 4; i++) {
        const int c = i * 256 + t;
        const int row = c >> 3, c8 = (c & 7) << 3;
        __pipeline_memcpy_async(&Qs[row*HLD + c8], &Qg[row*64 + c8], 16);
    }
    issueKV(0);

    __pipeline_wait_prior(0);
    __syncthreads();

    unsigned qf[4][4];
    {
        const unsigned qb = (unsigned)__cvta_generic_to_shared(Qs);
        const int qrow = rb*16 + (lane & 15);
        const int qcoff = (lane >> 4) * 8;
        const __half2 qscale = __float2half2_rn(0.18033688f);  // log2(e)/8
        #pragma unroll
        for (int kc = 0; kc < 4; kc++) {
            ldsm4(qf[kc], qb + (unsigned)(qrow*HLD + kc*16 + qcoff) * 2u);
            #pragma unroll
            for (int j = 0; j < 4; j++) {
                __half2 v = *(__half2*)&qf[kc][j];
                v = __hmul2(v, qscale);
                qf[kc][j] = *(unsigned*)&v;
            }
        }
    }

    float yacc[8][4];
    #pragma unroll
    for (int i = 0; i < 8; i++)
        #pragma unroll
        for (int j = 0; j < 4; j++) yacc[i][j] = 0.f;
    float rs0 = 0.f, rs1 = 0.f;

    const unsigned kvb = (unsigned)__cvta_generic_to_shared(KV);
    const int krow  = ((lane >> 4) << 3) + (lane & 7);
    const int kcoff = ((lane >> 3) & 1) * 8;
    const int row0  = rb*16 + g;
    const int qabs0 = qt*128 + row0;

    for (int st = 0; st < nkt; st++) {
        if (st > 0) {
            __pipeline_wait_prior(0);
            __syncthreads();
        }
        if (st + 1 < nkt) issueKV(st + 1);

        const unsigned KsB = kvb + (unsigned)((st & 1) * 2 * KVT2) * 2u;
        const unsigned VsB = KsB + (unsigned)KVT2 * 2u;
        const bool diag = (st == nkt - 1);

        #pragma unroll
        for (int sub = 0; sub < 2; sub++) {
            if (diag && sub == 1 && rb < 4) break;

            const unsigned Kb32 = KsB + (unsigned)(sub * 64 * HLD) * 2u;
            const unsigned Vb32 = VsB + (unsigned)(sub * 64 * HLD) * 2u;

            // S = Q @ K^T, FP16 accumulate. sacc[nb] = {row g pair, row g+8 pair}.
            unsigned sacc[8][2];
            #pragma unroll
            for (int i = 0; i < 8; i++) { sacc[i][0] = 0u; sacc[i][1] = 0u; }

            #pragma unroll
            for (int kc = 0; kc < 4; kc++) {
                const unsigned cb = (unsigned)(kc*16 + kcoff) * 2u;
                #pragma unroll
                for (int kb = 0; kb < 4; kb++) {
                    unsigned kf[4];
                    ldsm4(kf, Kb32 + (unsigned)((krow + kb*16)*HLD)*2u + cb);
                    mma16816h(sacc[kb*2],     qf[kc], kf[0], kf[1]);
                    mma16816h(sacc[kb*2 + 1], qf[kc], kf[2], kf[3]);
                }
            }

            // Causal mask on diagonal tile: add -30000 to masked cols (half2).
            if (diag) {
                const int kbase = st*128 + sub*64;
                #pragma unroll
                for (int nb = 0; nb < 8; nb++) {
                    const int cb = kbase + nb*8 + 2*tg;
                    __half2 m0 = __floats2half2_rn(cb > qabs0     ? -30000.f : 0.f,
                                                   cb + 1 > qabs0 ? -30000.f : 0.f);
                    __half2 m1 = __floats2half2_rn(cb > qabs0 + 8     ? -30000.f : 0.f,
                                                   cb + 1 > qabs0 + 8 ? -30000.f : 0.f);
                    __half2 v0 = __hadd2(*(__half2*)&sacc[nb][0], m0);
                    __half2 v1 = __hadd2(*(__half2*)&sacc[nb][1], m1);
                    sacc[nb][0] = *(unsigned*)&v0;
                    sacc[nb][1] = *(unsigned*)&v1;
                }
            }

            // P = 2^S directly on accumulator regs (already A-fragment layout):
            // pf[c] = {ex2(sacc[2c][0]), ex2(sacc[2c][1]),
            //          ex2(sacc[2c+1][0]), ex2(sacc[2c+1][1])}
            unsigned pf[4][4];
            #pragma unroll
            for (int c = 0; c < 4; c++) {
                pf[c][0] = hex2(sacc[2*c][0]);
                pf[c][1] = hex2(sacc[2*c][1]);
                pf[c][2] = hex2(sacc[2*c + 1][0]);
                pf[c][3] = hex2(sacc[2*c + 1][1]);
            }

            // Row sums (ALU pipe): regs {0,2} = row g -> rs0; {1,3} = row g+8.
            {
                __half2 a0 = __hadd2(__hadd2(*(__half2*)&pf[0][0], *(__half2*)&pf[0][2]),
                                     __hadd2(*(__half2*)&pf[1][0], *(__half2*)&pf[1][2]));
                __half2 a1 = __hadd2(__hadd2(*(__half2*)&pf[2][0], *(__half2*)&pf[2][2]),
                                     __hadd2(*(__half2*)&pf[3][0], *(__half2*)&pf[3][2]));
                __half2 s0 = __hadd2(a0, a1);
                rs0 += __low2float(s0) + __high2float(s0);

                __half2 b0 = __hadd2(__hadd2(*(__half2*)&pf[0][1], *(__half2*)&pf[0][3]),
                                     __hadd2(*(__half2*)&pf[1][1], *(__half2*)&pf[1][3]));
                __half2 b1 = __hadd2(__hadd2(*(__half2*)&pf[2][1], *(__half2*)&pf[2][3]),
                                     __hadd2(*(__half2*)&pf[3][1], *(__half2*)&pf[3][3]));
                __half2 s1 = __hadd2(b0, b1);
                rs1 += __low2float(s1) + __high2float(s1);
            }

            // Y += P @ V (f32 accumulate — K up to 2048).
            #pragma unroll
            for (int nd = 0; nd < 8; nd++) {
                unsigned vfA[4], vfB[4];
                ldsm4t(vfA, Vb32 + (unsigned)( lane      *HLD + nd*8) * 2u);
                ldsm4t(vfB, Vb32 + (unsigned)((lane + 32)*HLD + nd*8) * 2u);
                mma16816(yacc[nd], pf[0], vfA[0], vfA[1]);
                mma16816(yacc[nd], pf[1], vfA[2], vfA[3]);
                mma16816(yacc[nd], pf[2], vfB[0], vfB[1]);
                mma16816(yacc[nd], pf[3], vfB[2], vfB[3]);
            }
        }
    }

    // Complete row sums across the 4 quad lanes.
    rs0 += __shfl_xor_sync(0xffffffffu, rs0, 1);
    rs0 += __shfl_xor_sync(0xffffffffu, rs0, 2);
    rs1 += __shfl_xor_sync(0xffffffffu, rs1, 1);
    rs1 += __shfl_xor_sync(0xffffffffu, rs1, 2);
    const float inv0 = 1.f / rs0;
    const float inv1 = 1.f / rs1;

    const int b = bh >> 4, h = bh & 15;
    const int q0 = qt*128 + row0;
    __half* yo0 = y + ((size_t)(b * CS + q0)) * CD + h*64;
    __half* yo1 = yo0 + (size_t)8 * CD;
    #pragma unroll
    for (int nd = 0; nd < 8; nd++) {
        const int col = nd*8 + 2*tg;
        __half2 h0 = __floats2half2_rn(yacc[nd][0]*inv0, yacc[nd][1]*inv0);
        __half2 h1 = __floats2half2_rn(yacc[nd][2]*inv1, yacc[nd][3]*inv1);
        *(__half2*)&yo0[col] = h0;
        *(__half2*)&yo1[col] = h1;
    }
}

// ---------------------------------------------------------------------------
extern "C" void kernel_launch(void* const* d_in, const int* in_sizes, int n_in,
                              void* d_out, int out_size)
{
    const float* x  = (const float*)d_in[0];
    const float* Wa = (const float*)d_in[1];
    const float* ba = (const float*)d_in[2];
    const float* Wp = (const float*)d_in[3];
    const float* bp = (const float*)d_in[4];
    float* out = (float*)d_out;

    __half *qkv, *y, *xh, *wa, *wp;
    cudaGetSymbolAddress((void**)&qkv, g_qkv);
    cudaGetSymbolAddress((void**)&y,   g_y);
    cudaGetSymbolAddress((void**)&xh,  g_xh);
    cudaGetSymbolAddress((void**)&wa,  g_wa);
    cudaGetSymbolAddress((void**)&wp,  g_wp);

    cudaFuncSetAttribute(gemm_h<0>,
        cudaFuncAttributeMaxDynamicSharedMemorySize, GEMM_SMEM);
    cudaFuncSetAttribute(gemm_h<1>,
        cudaFuncAttributeMaxDynamicSharedMemorySize, GEMM_SMEM);
    cudaFuncSetAttribute(attn_tc,
        cudaFuncAttributeMaxDynamicSharedMemorySize, ATTN_SMEM);

    const int ncv = N4_X + N4_WA + N4_WP;
    cvt_all_kernel<<<(ncv + 255)/256, 256>>>(x, Wa, Wp, xh, wa, wp);

    gemm_h<1><<<dim3(3*CD/128, CB*CS/128), 256, GEMM_SMEM>>>(
        xh, wa, ba, qkv, CB*CS, 3*CD, CD);
    attn_tc<<<dim3(CS/128, CBH), 256, ATTN_SMEM>>>(qkv, y);
    gemm_h<0><<<dim3(CD/128, CB*CS/128), 256, GEMM_SMEM>>>(
        y, wp, bp, out, CB*CS, CD, CD);
}